// round 3
// baseline (speedup 1.0000x reference)
#include <cuda_runtime.h>
#include <cuda_bf16.h>
#include <math.h>

// ---------------- problem constants ----------------
#define BATCH 2
#define HEADS 16
#define SEQ   4096
#define DIM   64
#define HID   1024
#define NHASH 2
#define NBUCK 128
#define CHUNK 64
#define BH    (BATCH*HEADS)          // 32
#define SH    (NHASH*SEQ)            // 8192
#define NCH   (SH/CHUNK)             // 128

// ---------------- scratch (device globals; no allocation allowed) ----------
__device__ float g_qk[BH*SEQ*DIM];          // [bh][s][d]  33.5 MB
__device__ float g_v [BH*SEQ*DIM];          // 33.5 MB
__device__ unsigned char  g_buckets[BH*SH]; // [bh][t], t = n*SEQ + s
__device__ unsigned short g_sorted[BH*SH];  // sorted position p -> t
__device__ unsigned short g_undo[BH*SH];    // t -> sorted position p
__device__ float g_outs[BH*SH*DIM];         // sorted-order outputs, 67 MB
__device__ float g_logits[BH*SH];           // sorted-order logits

// ---------------- SGEMM:  C = A[8192,1024] @ W[1024,1024]^T ---------------
// Epilogue writes into g_qk/g_v with [b][h][s][d] layout.
__global__ __launch_bounds__(256) void sgemm_kernel(
    const float* __restrict__ A, const float* __restrict__ W, int which)
{
    const int K = HID;
    __shared__ float As[16][128];
    __shared__ float Bs[16][128];
    float* Cdst = which ? g_v : g_qk;

    int bn = blockIdx.x;          // 0..7   (N=1024 / 128)
    int bm = blockIdx.y;          // 0..63  (M=8192 / 128)
    int tid = threadIdx.x;
    int tx = tid & 15;
    int ty = tid >> 4;

    float acc[8][8];
#pragma unroll
    for (int i = 0; i < 8; i++)
#pragma unroll
        for (int j = 0; j < 8; j++) acc[i][j] = 0.f;

    const float* Abase = A + (bm*128)*K;
    const float* Wbase = W + (bn*128)*K;
    int lr0 = tid >> 2;
    int lc0 = (tid & 3) * 4;

    for (int k0 = 0; k0 < K; k0 += 16) {
#pragma unroll
        for (int i = 0; i < 2; i++) {
            int r = lr0 + i*64;
            float4 va = *(const float4*)(Abase + r*K + k0 + lc0);
            As[lc0+0][r] = va.x; As[lc0+1][r] = va.y;
            As[lc0+2][r] = va.z; As[lc0+3][r] = va.w;
            float4 vb = *(const float4*)(Wbase + r*K + k0 + lc0);
            Bs[lc0+0][r] = vb.x; Bs[lc0+1][r] = vb.y;
            Bs[lc0+2][r] = vb.z; Bs[lc0+3][r] = vb.w;
        }
        __syncthreads();
#pragma unroll
        for (int k = 0; k < 16; k++) {
            float a[8], b[8];
#pragma unroll
            for (int i = 0; i < 8; i++) a[i] = As[k][ty*8+i];
#pragma unroll
            for (int j = 0; j < 8; j++) b[j] = Bs[k][tx*8+j];
#pragma unroll
            for (int i = 0; i < 8; i++)
#pragma unroll
                for (int j = 0; j < 8; j++) acc[i][j] += a[i]*b[j];
        }
        __syncthreads();
    }

#pragma unroll
    for (int i = 0; i < 8; i++) {
        int m = bm*128 + ty*8 + i;
        int b = m >> 12, s = m & 4095;
#pragma unroll
        for (int j = 0; j < 8; j++) {
            int n = bn*128 + tx*8 + j;
            int h = n >> 6, d = n & 63;
            Cdst[((b*HEADS + h)*SEQ + s)*DIM + d] = acc[i][j];
        }
    }
}

// ---------------- hashing: argmax over [rot, -rot] per hash round ----------
// One block = 8 tokens; rotations staged in shared (32 KB).
// thread = (n, r): n = tid>>6 hash round, r = tid&63 rotation column.
#define HTOK 8
__global__ __launch_bounds__(128) void hash_kernel(const float* __restrict__ rot)
{
    __shared__ float rs[DIM*128];       // rot[d][n][r] flattened, 32 KB
    __shared__ float q[HTOK][DIM];
    __shared__ float sv[HTOK][4];
    __shared__ int   si[HTOK][4];

    int tid = threadIdx.x;
    int g0  = blockIdx.x * HTOK;        // first token row in g_qk

    for (int i = tid; i < DIM*128; i += 128) rs[i] = rot[i];
#pragma unroll
    for (int t = 0; t < HTOK; t++) {
        int d = tid & 63, half = tid >> 6;
        if (half == 0) q[t][d] = g_qk[(g0 + t)*DIM + d];
    }
    __syncthreads();

    int warp = tid >> 5, lane = tid & 31;

#pragma unroll
    for (int t = 0; t < HTOK; t++) {
        float val = 0.f;
#pragma unroll
        for (int d = 0; d < DIM; d++) val += q[t][d] * rs[d*128 + tid];

        int r = tid & 63;
        float bv; int bi;
        if (val >= -val) { bv = val;  bi = r; }
        else             { bv = -val; bi = r + 64; }
#pragma unroll
        for (int off = 16; off; off >>= 1) {
            float ov = __shfl_down_sync(0xffffffffu, bv, off);
            int   oi = __shfl_down_sync(0xffffffffu, bi, off);
            if (ov > bv || (ov == bv && oi < bi)) { bv = ov; bi = oi; }
        }
        if (lane == 0) { sv[t][warp] = bv; si[t][warp] = bi; }
    }
    __syncthreads();

    // two tokens finalized per thread pair group: use first 16 threads
    if (tid < HTOK*2) {
        int t = tid >> 1, n = tid & 1;
        float v0 = sv[t][n*2];   int i0 = si[t][n*2];
        float v1 = sv[t][n*2+1]; int i1 = si[t][n*2+1];
        if (v1 > v0 || (v1 == v0 && i1 < i0)) { v0 = v1; i0 = i1; }
        int bucket = i0 + n*NBUCK;
        int gidx = g0 + t;
        int bh = gidx >> 12;
        int s  = gidx & 4095;
        g_buckets[bh*SH + n*SEQ + s] = (unsigned char)bucket;
    }
}

// ---------------- stable counting sort per (b,h) ---------------------------
// Must equal stable argsort of S*bucket + (t % S): (bucket, pos, round) asc.
__global__ __launch_bounds__(256) void sort_kernel()
{
    int bh = blockIdx.x;
    __shared__ unsigned char bk[SH];
    __shared__ unsigned int  gh[32][256];   // per-group histograms / offsets
    __shared__ unsigned int  hist[256];
    int tid = threadIdx.x;

    const unsigned char* src = &g_buckets[bh*SH];
    for (int i = tid; i < SH; i += 256) bk[i] = src[i];
    for (int g = 0; g < 32; g++) gh[g][tid] = 0;
    __syncthreads();

    // group histograms (8 threads per group, enumeration idx = pos*2 + round)
    {
        int g = tid >> 3, lane = tid & 7;
        for (int k = 0; k < 32; k++) {
            int idx = g*256 + lane + k*8;
            int pos = idx >> 1, n = idx & 1;
            atomicAdd(&gh[g][bk[n*SEQ + pos]], 1u);
        }
    }
    __syncthreads();

    // column-wise exclusive scan over groups (thread = bucket)
    {
        unsigned int running = 0;
        for (int g = 0; g < 32; g++) {
            unsigned int t = gh[g][tid];
            gh[g][tid] = running;
            running += t;
        }
        hist[tid] = running;
    }
    __syncthreads();
    if (tid == 0) {
        unsigned int acc = 0;
        for (int b = 0; b < 256; b++) { unsigned int t = hist[b]; hist[b] = acc; acc += t; }
    }
    __syncthreads();
    for (int g = 0; g < 32; g++) gh[g][tid] += hist[tid];
    __syncthreads();

    // stable scatter: one thread per group, serial in enumeration order
    if (tid < 32) {
        unsigned short* outS = &g_sorted[bh*SH];
        unsigned short* outU = &g_undo[bh*SH];
        for (int i = 0; i < 256; i++) {
            int idx = tid*256 + i;
            int pos = idx >> 1, n = idx & 1;
            int t = n*SEQ + pos;
            int b = bk[t];
            unsigned int dest = gh[tid][b]++;
            outS[dest] = (unsigned short)t;
            outU[t]    = (unsigned short)dest;
        }
    }
}

// ---------------- chunked attention ---------------------------------------
// grid = BH*NCH, block = 128. K window = [prev chunk | cur chunk] (wrap).
#define KS_PITCH 65
#define DS_PITCH 129
#define ATTN_SMEM ((128*KS_PITCH + 128*KS_PITCH + 64*DS_PITCH + 128 + 64)*4 + 128*4)

__global__ __launch_bounds__(128) void attn_kernel()
{
    extern __shared__ float sm[];
    float* Ks     = sm;                       // 128 x 65 (raw qk of k-rows)
    float* Vs     = Ks + 128*KS_PITCH;        // 128 x 65
    float* Ds     = Vs + 128*KS_PITCH;        // 64 x 129 (dots -> probs)
    float* rnorm  = Ds + 64*DS_PITCH;         // 128
    float* rowlog = rnorm + 128;              // 64
    int*   tick   = (int*)(rowlog + 64);      // 128

    int chunk = blockIdx.x & (NCH-1);
    int bh    = blockIdx.x >> 7;
    int tid   = threadIdx.x;

    // ticks for 128 k-rows (rows 64..127 are the current/query chunk)
    {
        int sp = (chunk*CHUNK + (SH - CHUNK) + tid) & (SH-1);
        int t  = g_sorted[bh*SH + sp];
        tick[tid] = t & (SEQ-1);
    }
    __syncthreads();

    // cooperative row loads (coalesced: 2 rows per iteration)
    for (int rr = 0; rr < 128; rr += 2) {
        int row = rr + (tid >> 6);
        int d   = tid & 63;
        int s   = tick[row];
        int base = (bh*SEQ + s)*DIM + d;
        Ks[row*KS_PITCH + d] = g_qk[base];
        Vs[row*KS_PITCH + d] = g_v[base];
    }
    __syncthreads();

    // per-row key norm factor
    {
        float ss = 0.f;
#pragma unroll
        for (int d = 0; d < DIM; d++) { float x = Ks[tid*KS_PITCH + d]; ss += x*x; }
        rnorm[tid] = rsqrtf(ss * (1.0f/DIM) + 1e-6f) * 0.125f;  // /sqrt(64)
    }
    __syncthreads();

    int qi   = tid >> 1;
    int half = tid & 1;

    // Q row in registers
    float qreg[DIM];
#pragma unroll
    for (int d = 0; d < DIM; d++) qreg[d] = Ks[(64+qi)*KS_PITCH + d];
    int tq = tick[64 + qi];

    // dots (64 columns per thread) + masks
    for (int j = 0; j < 64; j++) {
        int kc = half*64 + j;
        float acc = 0.f;
#pragma unroll
        for (int d = 0; d < DIM; d++) acc += qreg[d] * Ks[kc*KS_PITCH + d];
        acc *= rnorm[kc];
        int tk = tick[kc];
        if (tq < tk)  acc = -1e9f;
        if (tq == tk) acc = -1e5f;
        Ds[qi*DS_PITCH + kc] = acc;
    }
    __syncthreads();

    // logsumexp per q row
    if (tid < 64) {
        float m = -3.4e38f;
        for (int kc = 0; kc < 128; kc++) m = fmaxf(m, Ds[tid*DS_PITCH + kc]);
        float s = 0.f;
        for (int kc = 0; kc < 128; kc++) s += __expf(Ds[tid*DS_PITCH + kc] - m);
        rowlog[tid] = m + __logf(s);
    }
    __syncthreads();

    // probs
    {
        float lg = rowlog[qi];
        for (int j = 0; j < 64; j++) {
            int kc = half*64 + j;
            Ds[qi*DS_PITCH + kc] = __expf(Ds[qi*DS_PITCH + kc] - lg);
        }
    }
    __syncthreads();

    // out = probs @ V  (32 output dims per thread)
    {
        float acc[32];
#pragma unroll
        for (int j = 0; j < 32; j++) acc[j] = 0.f;
        int d0 = half*32;
        for (int kc = 0; kc < 128; kc++) {
            float p = Ds[qi*DS_PITCH + kc];
#pragma unroll
            for (int j = 0; j < 32; j++) acc[j] += p * Vs[kc*KS_PITCH + d0 + j];
        }
        float* o = &g_outs[(bh*SH + chunk*CHUNK + qi)*DIM + d0];
#pragma unroll
        for (int j = 0; j < 32; j++) o[j] = acc[j];
        if (half == 0) g_logits[bh*SH + chunk*CHUNK + qi] = rowlog[qi];
    }
}

// ---------------- combine hash rounds + write output -----------------------
__global__ __launch_bounds__(256) void combine_kernel(float* __restrict__ out)
{
    int i = blockIdx.x*256 + threadIdx.x;     // over BH*SEQ*DIM = 8.4M
    int d  = i & 63;
    int r  = i >> 6;
    int s  = r & (SEQ-1);
    int bh = r >> 12;
    int base = bh*SH;

    int p0 = g_undo[base + s];
    int p1 = g_undo[base + SEQ + s];
    float l0 = g_logits[base + p0];
    float l1 = g_logits[base + p1];
    float m  = fmaxf(l0, l1);
    float w0 = __expf(l0 - m);
    float w1 = __expf(l1 - m);
    float inv = 1.0f / (w0 + w1);
    float o = (w0 * g_outs[(base + p0)*DIM + d] +
               w1 * g_outs[(base + p1)*DIM + d]) * inv;

    int b = bh >> 4, h = bh & 15;
    out[(b*SEQ + s)*(HEADS*DIM) + h*DIM + d] = o;
}

// ---------------- launch ---------------------------------------------------
extern "C" void kernel_launch(void* const* d_in, const int* in_sizes, int n_in,
                              void* d_out, int out_size)
{
    const float* hidden = (const float*)d_in[0];
    const float* Wqk    = (const float*)d_in[1];
    const float* Wv     = (const float*)d_in[2];
    const float* rot    = (const float*)d_in[3];
    float* out = (float*)d_out;

    static int attn_attr_set = 0;
    if (!attn_attr_set) {
        cudaFuncSetAttribute(attn_kernel,
                             cudaFuncAttributeMaxDynamicSharedMemorySize, ATTN_SMEM);
        attn_attr_set = 1;
    }

    dim3 gg(8, 64);
    sgemm_kernel<<<gg, 256>>>(hidden, Wqk, 0);
    sgemm_kernel<<<gg, 256>>>(hidden, Wv, 1);
    hash_kernel<<<(BH*SEQ)/HTOK, 128>>>(rot);
    sort_kernel<<<BH, 256>>>();
    attn_kernel<<<BH*NCH, 128, ATTN_SMEM>>>();
    combine_kernel<<<(BH*SEQ*DIM)/256, 256>>>(out);
}

// round 4
// speedup vs baseline: 2.0436x; 2.0436x over previous
#include <cuda_runtime.h>
#include <cuda_bf16.h>
#include <math.h>

// ---------------- problem constants ----------------
#define BATCH 2
#define HEADS 16
#define SEQ   4096
#define DIM   64
#define HID   1024
#define NHASH 2
#define NBUCK 128
#define CHUNK 64
#define BH    (BATCH*HEADS)          // 32
#define SH    (NHASH*SEQ)            // 8192
#define NCH   (SH/CHUNK)             // 128

// ---------------- scratch (device globals; no allocation allowed) ----------
__device__ float g_qk[BH*SEQ*DIM];
__device__ float g_v [BH*SEQ*DIM];
__device__ unsigned char  g_buckets[BH*SH];
__device__ unsigned short g_sorted[BH*SH];
__device__ unsigned short g_undo[BH*SH];
__device__ float g_outs[BH*SH*DIM];
__device__ float g_logits[BH*SH];

// ---------------- SGEMM:  C = A[8192,1024] @ W[1024,1024]^T ---------------
// Double-buffered BK=8, 128x128 tile, 256 threads, 8x8 micro-tile.
// gridDim.z selects (Wqk -> g_qk) or (Wv -> g_v).
__global__ __launch_bounds__(256) void sgemm_kernel(
    const float* __restrict__ A, const float* __restrict__ Wqk,
    const float* __restrict__ Wv)
{
    const int K = HID;
    __shared__ float As[2][8][132];
    __shared__ float Bs[2][8][132];

    const float* W = blockIdx.z ? Wv : Wqk;
    float* Cdst    = blockIdx.z ? g_v : g_qk;

    int bn = blockIdx.x;          // 0..7
    int bm = blockIdx.y;          // 0..63
    int tid = threadIdx.x;
    int tx = tid & 15;
    int ty = tid >> 4;

    int lrow = tid >> 1;
    int kq   = (tid & 1) * 4;
    const float* Aptr = A + ((long)(bm*128 + lrow))*K + kq;
    const float* Wptr = W + ((long)(bn*128 + lrow))*K + kq;

    float acc[8][8];
#pragma unroll
    for (int i = 0; i < 8; i++)
#pragma unroll
        for (int j = 0; j < 8; j++) acc[i][j] = 0.f;

    // stage 0
    {
        float4 pa = *(const float4*)(Aptr);
        float4 pb = *(const float4*)(Wptr);
        As[0][kq+0][lrow] = pa.x; As[0][kq+1][lrow] = pa.y;
        As[0][kq+2][lrow] = pa.z; As[0][kq+3][lrow] = pa.w;
        Bs[0][kq+0][lrow] = pb.x; Bs[0][kq+1][lrow] = pb.y;
        Bs[0][kq+2][lrow] = pb.z; Bs[0][kq+3][lrow] = pb.w;
    }
    __syncthreads();

    int stage = 0;
#pragma unroll 1
    for (int k0 = 0; k0 < K; k0 += 8) {
        bool has = (k0 + 8) < K;
        float4 pa, pb;
        if (has) {
            pa = *(const float4*)(Aptr + k0 + 8);
            pb = *(const float4*)(Wptr + k0 + 8);
        }
#pragma unroll
        for (int k = 0; k < 8; k++) {
            float a[8], b[8];
            *(float4*)(a)   = *(const float4*)&As[stage][k][ty*8];
            *(float4*)(a+4) = *(const float4*)&As[stage][k][ty*8+4];
            *(float4*)(b)   = *(const float4*)&Bs[stage][k][tx*4];
            *(float4*)(b+4) = *(const float4*)&Bs[stage][k][64 + tx*4];
#pragma unroll
            for (int i = 0; i < 8; i++)
#pragma unroll
                for (int j = 0; j < 8; j++) acc[i][j] += a[i]*b[j];
        }
        if (has) {
            int ns = stage ^ 1;
            As[ns][kq+0][lrow] = pa.x; As[ns][kq+1][lrow] = pa.y;
            As[ns][kq+2][lrow] = pa.z; As[ns][kq+3][lrow] = pa.w;
            Bs[ns][kq+0][lrow] = pb.x; Bs[ns][kq+1][lrow] = pb.y;
            Bs[ns][kq+2][lrow] = pb.z; Bs[ns][kq+3][lrow] = pb.w;
            __syncthreads();
            stage = ns;
        }
    }

#pragma unroll
    for (int i = 0; i < 8; i++) {
        int m = bm*128 + ty*8 + i;
        int b = m >> 12, s = m & 4095;
#pragma unroll
        for (int j = 0; j < 8; j++) {
            int n = bn*128 + ((j < 4) ? (tx*4 + j) : (64 + tx*4 + j - 4));
            int h = n >> 6, d = n & 63;
            Cdst[((b*HEADS + h)*SEQ + s)*DIM + d] = acc[i][j];
        }
    }
}

// ---------------- hashing: argmax over [rot, -rot] per hash round ----------
#define HTOK 32
__global__ __launch_bounds__(128) void hash_kernel(const float* __restrict__ rot)
{
    __shared__ float rs[DIM*128];       // 32 KB
    __shared__ float q[HTOK][DIM];      // 8 KB
    __shared__ float sv[HTOK][4];
    __shared__ int   si[HTOK][4];

    int tid = threadIdx.x;
    int g0  = blockIdx.x * HTOK;

    for (int i = tid; i < DIM*128; i += 128) rs[i] = rot[i];
    for (int i = tid; i < HTOK*DIM; i += 128) {
        int t = i >> 6, d = i & 63;
        q[t][d] = g_qk[(g0 + t)*DIM + d];
    }
    __syncthreads();

    int warp = tid >> 5, lane = tid & 31;
    int r = tid & 63;

#pragma unroll 4
    for (int t = 0; t < HTOK; t++) {
        float val = 0.f;
#pragma unroll
        for (int d = 0; d < DIM; d++) val += q[t][d] * rs[d*128 + tid];

        float bv; int bi;
        if (val >= -val) { bv = val;  bi = r; }
        else             { bv = -val; bi = r + 64; }
#pragma unroll
        for (int off = 16; off; off >>= 1) {
            float ov = __shfl_down_sync(0xffffffffu, bv, off);
            int   oi = __shfl_down_sync(0xffffffffu, bi, off);
            if (ov > bv || (ov == bv && oi < bi)) { bv = ov; bi = oi; }
        }
        if (lane == 0) { sv[t][warp] = bv; si[t][warp] = bi; }
    }
    __syncthreads();

    if (tid < HTOK*2) {
        int t = tid >> 1, n = tid & 1;
        float v0 = sv[t][n*2];   int i0 = si[t][n*2];
        float v1 = sv[t][n*2+1]; int i1 = si[t][n*2+1];
        if (v1 > v0 || (v1 == v0 && i1 < i0)) { v0 = v1; i0 = i1; }
        int bucket = i0 + n*NBUCK;
        int gidx = g0 + t;
        int bh = gidx >> 12;
        int s  = gidx & 4095;
        g_buckets[bh*SH + n*SEQ + s] = (unsigned char)bucket;
    }
}

// ---------------- stable counting sort per (b,h) ---------------------------
__global__ __launch_bounds__(256) void sort_kernel()
{
    int bh = blockIdx.x;
    __shared__ unsigned char bk[SH];
    __shared__ unsigned int  gh[32][256];
    __shared__ unsigned int  hist[256];
    int tid = threadIdx.x;

    const unsigned char* src = &g_buckets[bh*SH];
    for (int i = tid; i < SH; i += 256) bk[i] = src[i];
    for (int g = 0; g < 32; g++) gh[g][tid] = 0;
    __syncthreads();

    {
        int g = tid >> 3, lane = tid & 7;
        for (int k = 0; k < 32; k++) {
            int idx = g*256 + lane + k*8;
            int pos = idx >> 1, n = idx & 1;
            atomicAdd(&gh[g][bk[n*SEQ + pos]], 1u);
        }
    }
    __syncthreads();

    {
        unsigned int running = 0;
        for (int g = 0; g < 32; g++) {
            unsigned int t = gh[g][tid];
            gh[g][tid] = running;
            running += t;
        }
        hist[tid] = running;
    }
    __syncthreads();
    if (tid == 0) {
        unsigned int acc = 0;
        for (int b = 0; b < 256; b++) { unsigned int t = hist[b]; hist[b] = acc; acc += t; }
    }
    __syncthreads();
    for (int g = 0; g < 32; g++) gh[g][tid] += hist[tid];
    __syncthreads();

    if (tid < 32) {
        unsigned short* outS = &g_sorted[bh*SH];
        unsigned short* outU = &g_undo[bh*SH];
        for (int i = 0; i < 256; i++) {
            int idx = tid*256 + i;
            int pos = idx >> 1, n = idx & 1;
            int t = n*SEQ + pos;
            int b = bk[t];
            unsigned int dest = gh[tid][b]++;
            outS[dest] = (unsigned short)t;
            outU[t]    = (unsigned short)dest;
        }
    }
}

// ---------------- chunked attention ---------------------------------------
// Register-blocked: dots 16x4 tile over d-major Kt; PV 8x4 tile over Pt/Vs.
#define KT_PITCH 132
#define V_PITCH  68
#define P_PITCH  68
#define ATTN_SMEM ((64*KT_PITCH + 128*V_PITCH + 128*P_PITCH + 128 + 64 + 128)*4)

__global__ __launch_bounds__(128) void attn_kernel()
{
    extern __shared__ float sm[];
    float* kt     = sm;                         // [64 d][132 rows]
    float* vs     = kt + 64*KT_PITCH;           // [128 rows][68 d]
    float* pt     = vs + 128*V_PITCH;           // [128 kc][68 q]
    float* rnorm  = pt + 128*P_PITCH;           // 128
    float* rowlog = rnorm + 128;                // 64
    int*   tick   = (int*)(rowlog + 64);        // 128

    int chunk = blockIdx.x & (NCH-1);
    int bh    = blockIdx.x >> 7;
    int tid   = threadIdx.x;

    // ticks for 128 k-rows (rows 64..127 are the current/query chunk)
    {
        int sp = (chunk*CHUNK + (SH - CHUNK) + tid) & (SH-1);
        int t  = g_sorted[bh*SH + sp];
        tick[tid] = t & (SEQ-1);
    }
    __syncthreads();

    // cooperative loads: Kt transposed (d-major), Vs row-major
    for (int rr = 0; rr < 128; rr += 2) {
        int row = rr + (tid >> 6);
        int d   = tid & 63;
        int s   = tick[row];
        int base = (bh*SEQ + s)*DIM + d;
        kt[d*KT_PITCH + row] = g_qk[base];
        vs[row*V_PITCH + d]  = g_v[base];
    }
    __syncthreads();

    // per-row key norm factor
    {
        float ss = 0.f;
#pragma unroll
        for (int d = 0; d < DIM; d++) { float x = kt[d*KT_PITCH + tid]; ss += x*x; }
        rnorm[tid] = rsqrtf(ss * (1.0f/DIM) + 1e-6f) * 0.125f;
    }
    __syncthreads();

    int tx = tid & 15;     // q group (4 queries)
    int ty = tid >> 4;     // kc group (16 keys)

    // dots: D[kc 16][q 4] per thread
    {
        float acc[16][4];
#pragma unroll
        for (int i = 0; i < 16; i++)
#pragma unroll
            for (int j = 0; j < 4; j++) acc[i][j] = 0.f;

#pragma unroll 4
        for (int d = 0; d < DIM; d++) {
            float a[16], b[4];
            const float* kr = &kt[d*KT_PITCH];
            *(float4*)(a)    = *(const float4*)&kr[ty*16];
            *(float4*)(a+4)  = *(const float4*)&kr[ty*16+4];
            *(float4*)(a+8)  = *(const float4*)&kr[ty*16+8];
            *(float4*)(a+12) = *(const float4*)&kr[ty*16+12];
            *(float4*)(b)    = *(const float4*)&kr[64 + tx*4];
#pragma unroll
            for (int i = 0; i < 16; i++)
#pragma unroll
                for (int j = 0; j < 4; j++) acc[i][j] += a[i]*b[j];
        }

        int tq[4];
#pragma unroll
        for (int j = 0; j < 4; j++) tq[j] = tick[64 + tx*4 + j];

#pragma unroll
        for (int i = 0; i < 16; i++) {
            int kc = ty*16 + i;
            float rn = rnorm[kc];
            int tk = tick[kc];
            float4 o;
            float v0 = acc[i][0]*rn, v1 = acc[i][1]*rn,
                  v2 = acc[i][2]*rn, v3 = acc[i][3]*rn;
            if (tq[0] <  tk) v0 = -1e9f; else if (tq[0] == tk) v0 = -1e5f;
            if (tq[1] <  tk) v1 = -1e9f; else if (tq[1] == tk) v1 = -1e5f;
            if (tq[2] <  tk) v2 = -1e9f; else if (tq[2] == tk) v2 = -1e5f;
            if (tq[3] <  tk) v3 = -1e9f; else if (tq[3] == tk) v3 = -1e5f;
            o.x = v0; o.y = v1; o.z = v2; o.w = v3;
            *(float4*)&pt[kc*P_PITCH + tx*4] = o;
        }
    }
    __syncthreads();

    // softmax (logsumexp): row = tid>>1 over its 64-col half, shfl-combine
    {
        int row = tid >> 1, half = tid & 1;
        float m = -3.4e38f;
        for (int c = 0; c < 64; c++)
            m = fmaxf(m, pt[(half*64 + c)*P_PITCH + row]);
        m = fmaxf(m, __shfl_xor_sync(0xffffffffu, m, 1));
        float ssum = 0.f;
        for (int c = 0; c < 64; c++)
            ssum += __expf(pt[(half*64 + c)*P_PITCH + row] - m);
        ssum += __shfl_xor_sync(0xffffffffu, ssum, 1);
        float lg = m + __logf(ssum);
        if (half == 0) rowlog[row] = lg;
        for (int c = 0; c < 64; c++) {
            int idx = (half*64 + c)*P_PITCH + row;
            pt[idx] = __expf(pt[idx] - lg);
        }
    }
    __syncthreads();

    // PV: O[q 8][d 4] per thread (ty -> q rows, tx -> d cols)
    {
        float acc2[8][4];
#pragma unroll
        for (int i = 0; i < 8; i++)
#pragma unroll
            for (int j = 0; j < 4; j++) acc2[i][j] = 0.f;

#pragma unroll 4
        for (int kc = 0; kc < 128; kc++) {
            float a2[8], b2[4];
            *(float4*)(a2)   = *(const float4*)&pt[kc*P_PITCH + ty*8];
            *(float4*)(a2+4) = *(const float4*)&pt[kc*P_PITCH + ty*8+4];
            *(float4*)(b2)   = *(const float4*)&vs[kc*V_PITCH + tx*4];
#pragma unroll
            for (int i = 0; i < 8; i++)
#pragma unroll
                for (int j = 0; j < 4; j++) acc2[i][j] += a2[i]*b2[j];
        }

#pragma unroll
        for (int i = 0; i < 8; i++) {
            int q = ty*8 + i;
            float4 o; o.x = acc2[i][0]; o.y = acc2[i][1];
                      o.z = acc2[i][2]; o.w = acc2[i][3];
            *(float4*)&g_outs[((long)(bh*SH + chunk*CHUNK + q))*DIM + tx*4] = o;
        }
        if (tid < 64)
            g_logits[bh*SH + chunk*CHUNK + tid] = rowlog[tid];
    }
}

// ---------------- combine hash rounds + write output -----------------------
__global__ __launch_bounds__(256) void combine_kernel(float* __restrict__ out)
{
    int i = blockIdx.x*256 + threadIdx.x;
    int d  = i & 63;
    int r  = i >> 6;
    int s  = r & (SEQ-1);
    int bh = r >> 12;
    int base = bh*SH;

    int p0 = g_undo[base + s];
    int p1 = g_undo[base + SEQ + s];
    float l0 = g_logits[base + p0];
    float l1 = g_logits[base + p1];
    float m  = fmaxf(l0, l1);
    float w0 = __expf(l0 - m);
    float w1 = __expf(l1 - m);
    float inv = 1.0f / (w0 + w1);
    float o = (w0 * g_outs[(base + p0)*DIM + d] +
               w1 * g_outs[(base + p1)*DIM + d]) * inv;

    int b = bh >> 4, h = bh & 15;
    out[(b*SEQ + s)*(HEADS*DIM) + h*DIM + d] = o;
}

// ---------------- launch ---------------------------------------------------
extern "C" void kernel_launch(void* const* d_in, const int* in_sizes, int n_in,
                              void* d_out, int out_size)
{
    const float* hidden = (const float*)d_in[0];
    const float* Wqk    = (const float*)d_in[1];
    const float* Wv     = (const float*)d_in[2];
    const float* rot    = (const float*)d_in[3];
    float* out = (float*)d_out;

    static int attr_set = 0;
    if (!attr_set) {
        cudaFuncSetAttribute(attn_kernel,
                             cudaFuncAttributeMaxDynamicSharedMemorySize, ATTN_SMEM);
        attr_set = 1;
    }

    sgemm_kernel<<<dim3(8,64,2), 256>>>(hidden, Wqk, Wv);
    hash_kernel<<<(BH*SEQ)/HTOK, 128>>>(rot);
    sort_kernel<<<BH, 256>>>();
    attn_kernel<<<BH*NCH, 128, ATTN_SMEM>>>();
    combine_kernel<<<(BH*SEQ*DIM)/256, 256>>>(out);
}

// round 6
// speedup vs baseline: 2.1936x; 1.0734x over previous
#include <cuda_runtime.h>
#include <cuda_bf16.h>
#include <math.h>

// ---------------- problem constants ----------------
#define BATCH 2
#define HEADS 16
#define SEQ   4096
#define DIM   64
#define HID   1024
#define NHASH 2
#define NBUCK 128
#define CHUNK 64
#define BH    (BATCH*HEADS)          // 32
#define SH    (NHASH*SEQ)            // 8192
#define NCH   (SH/CHUNK)             // 128

// ---------------- scratch (device globals; no allocation allowed) ----------
__device__ float g_qk[BH*SEQ*DIM];
__device__ float g_v [BH*SEQ*DIM];
__device__ unsigned char  g_buckets[BH*SH];
__device__ unsigned short g_sorted[BH*SH];
__device__ unsigned short g_undo[BH*SH];
__device__ float g_outs[BH*SH*DIM];
__device__ float g_logits[BH*SH];

// ---------------- SGEMM:  C = A[8192,1024] @ W[1024,1024]^T ---------------
// Double-buffered BK=8, 128x128 tile, 256 threads, 8x8 micro-tile.
// gridDim.z selects (Wqk -> g_qk) or (Wv -> g_v).
__global__ __launch_bounds__(256) void sgemm_kernel(
    const float* __restrict__ A, const float* __restrict__ Wqk,
    const float* __restrict__ Wv)
{
    const int K = HID;
    __shared__ float As[2][8][132];
    __shared__ float Bs[2][8][132];

    const float* W = blockIdx.z ? Wv : Wqk;
    float* Cdst    = blockIdx.z ? g_v : g_qk;

    int bn = blockIdx.x;          // 0..7
    int bm = blockIdx.y;          // 0..63
    int tid = threadIdx.x;
    int tx = tid & 15;
    int ty = tid >> 4;

    int lrow = tid >> 1;
    int kq   = (tid & 1) * 4;
    const float* Aptr = A + ((long)(bm*128 + lrow))*K + kq;
    const float* Wptr = W + ((long)(bn*128 + lrow))*K + kq;

    float acc[8][8];
#pragma unroll
    for (int i = 0; i < 8; i++)
#pragma unroll
        for (int j = 0; j < 8; j++) acc[i][j] = 0.f;

    // stage 0
    {
        float4 pa = *(const float4*)(Aptr);
        float4 pb = *(const float4*)(Wptr);
        As[0][kq+0][lrow] = pa.x; As[0][kq+1][lrow] = pa.y;
        As[0][kq+2][lrow] = pa.z; As[0][kq+3][lrow] = pa.w;
        Bs[0][kq+0][lrow] = pb.x; Bs[0][kq+1][lrow] = pb.y;
        Bs[0][kq+2][lrow] = pb.z; Bs[0][kq+3][lrow] = pb.w;
    }
    __syncthreads();

    int stage = 0;
#pragma unroll 1
    for (int k0 = 0; k0 < K; k0 += 8) {
        bool has = (k0 + 8) < K;
        float4 pa, pb;
        if (has) {
            pa = *(const float4*)(Aptr + k0 + 8);
            pb = *(const float4*)(Wptr + k0 + 8);
        }
#pragma unroll
        for (int k = 0; k < 8; k++) {
            float a[8], b[8];
            *(float4*)(a)   = *(const float4*)&As[stage][k][ty*8];
            *(float4*)(a+4) = *(const float4*)&As[stage][k][ty*8+4];
            *(float4*)(b)   = *(const float4*)&Bs[stage][k][tx*4];
            *(float4*)(b+4) = *(const float4*)&Bs[stage][k][64 + tx*4];
#pragma unroll
            for (int i = 0; i < 8; i++)
#pragma unroll
                for (int j = 0; j < 8; j++) acc[i][j] += a[i]*b[j];
        }
        if (has) {
            int ns = stage ^ 1;
            As[ns][kq+0][lrow] = pa.x; As[ns][kq+1][lrow] = pa.y;
            As[ns][kq+2][lrow] = pa.z; As[ns][kq+3][lrow] = pa.w;
            Bs[ns][kq+0][lrow] = pb.x; Bs[ns][kq+1][lrow] = pb.y;
            Bs[ns][kq+2][lrow] = pb.z; Bs[ns][kq+3][lrow] = pb.w;
            __syncthreads();
            stage = ns;
        }
    }

    // vectorized epilogue: columns tx*4.. and 64+tx*4.. are d-contiguous
#pragma unroll
    for (int i = 0; i < 8; i++) {
        int m = bm*128 + ty*8 + i;
        int b = m >> 12, s = m & 4095;
        int n0 = bn*128 + tx*4;        // h = n0>>6, d = n0&63 (4 contiguous)
        int n1 = n0 + 64;
        float4 o0 = make_float4(acc[i][0], acc[i][1], acc[i][2], acc[i][3]);
        float4 o1 = make_float4(acc[i][4], acc[i][5], acc[i][6], acc[i][7]);
        *(float4*)&Cdst[((b*HEADS + (n0>>6))*SEQ + s)*DIM + (n0&63)] = o0;
        *(float4*)&Cdst[((b*HEADS + (n1>>6))*SEQ + s)*DIM + (n1&63)] = o1;
    }
}

// ---------------- hashing: argmax over [rot, -rot] per hash round ----------
#define HTOK 32
__global__ __launch_bounds__(128) void hash_kernel(const float* __restrict__ rot)
{
    __shared__ float rs[DIM*128];       // 32 KB
    __shared__ float q[HTOK][DIM];      // 8 KB
    __shared__ float sv[HTOK][4];
    __shared__ int   si[HTOK][4];

    int tid = threadIdx.x;
    int g0  = blockIdx.x * HTOK;

    for (int i = tid; i < DIM*128; i += 128) rs[i] = rot[i];
    for (int i = tid; i < HTOK*DIM; i += 128) {
        int t = i >> 6, d = i & 63;
        q[t][d] = g_qk[(g0 + t)*DIM + d];
    }
    __syncthreads();

    int warp = tid >> 5, lane = tid & 31;
    int r = tid & 63;

#pragma unroll 4
    for (int t = 0; t < HTOK; t++) {
        float val = 0.f;
#pragma unroll
        for (int d = 0; d < DIM; d++) val += q[t][d] * rs[d*128 + tid];

        float bv; int bi;
        if (val >= -val) { bv = val;  bi = r; }
        else             { bv = -val; bi = r + 64; }
#pragma unroll
        for (int off = 16; off; off >>= 1) {
            float ov = __shfl_down_sync(0xffffffffu, bv, off);
            int   oi = __shfl_down_sync(0xffffffffu, bi, off);
            if (ov > bv || (ov == bv && oi < bi)) { bv = ov; bi = oi; }
        }
        if (lane == 0) { sv[t][warp] = bv; si[t][warp] = bi; }
    }
    __syncthreads();

    if (tid < HTOK*2) {
        int t = tid >> 1, n = tid & 1;
        float v0 = sv[t][n*2];   int i0 = si[t][n*2];
        float v1 = sv[t][n*2+1]; int i1 = si[t][n*2+1];
        if (v1 > v0 || (v1 == v0 && i1 < i0)) { v0 = v1; i0 = i1; }
        int bucket = i0 + n*NBUCK;
        int gidx = g0 + t;
        int bh = gidx >> 12;
        int s  = gidx & 4095;
        g_buckets[bh*SH + n*SEQ + s] = (unsigned char)bucket;
    }
}

// ---------------- stable counting sort per (b,h) ---------------------------
__global__ __launch_bounds__(256) void sort_kernel()
{
    int bh = blockIdx.x;
    __shared__ unsigned char bk[SH];
    __shared__ unsigned int  gh[32][256];
    __shared__ unsigned int  hist[256];
    int tid = threadIdx.x;

    const unsigned char* src = &g_buckets[bh*SH];
    for (int i = tid; i < SH; i += 256) bk[i] = src[i];
    for (int g = 0; g < 32; g++) gh[g][tid] = 0;
    __syncthreads();

    {
        int g = tid >> 3, lane = tid & 7;
        for (int k = 0; k < 32; k++) {
            int idx = g*256 + lane + k*8;
            int pos = idx >> 1, n = idx & 1;
            atomicAdd(&gh[g][bk[n*SEQ + pos]], 1u);
        }
    }
    __syncthreads();

    {
        unsigned int running = 0;
        for (int g = 0; g < 32; g++) {
            unsigned int t = gh[g][tid];
            gh[g][tid] = running;
            running += t;
        }
        hist[tid] = running;
    }
    __syncthreads();
    if (tid == 0) {
        unsigned int acc = 0;
        for (int b = 0; b < 256; b++) { unsigned int t = hist[b]; hist[b] = acc; acc += t; }
    }
    __syncthreads();
    for (int g = 0; g < 32; g++) gh[g][tid] += hist[tid];
    __syncthreads();

    if (tid < 32) {
        unsigned short* outS = &g_sorted[bh*SH];
        unsigned short* outU = &g_undo[bh*SH];
        for (int i = 0; i < 256; i++) {
            int idx = tid*256 + i;
            int pos = idx >> 1, n = idx & 1;
            int t = n*SEQ + pos;
            int b = bk[t];
            unsigned int dest = gh[tid][b]++;
            outS[dest] = (unsigned short)t;
            outU[t]    = (unsigned short)dest;
        }
    }
}

// ---------------- chunked attention ---------------------------------------
// 256 threads. dots: 8kx4q/thread; softmax: 4 threads/row; PV: 4qx4d/thread.
#define KT_PITCH 132
#define V_PITCH  68
#define P_PITCH  68
#define ATTN_SMEM ((64*KT_PITCH + 128*V_PITCH + 128*P_PITCH + 128 + 64 + 128)*4)

__global__ __launch_bounds__(256) void attn_kernel()
{
    extern __shared__ float sm[];
    float* kt     = sm;                         // [64 d][132 rows]
    float* vs     = kt + 64*KT_PITCH;           // [128 rows][68 d]
    float* pt     = vs + 128*V_PITCH;           // [128 kc][68 q]
    float* rnorm  = pt + 128*P_PITCH;           // 128
    float* rowlog = rnorm + 128;                // 64
    int*   tick   = (int*)(rowlog + 64);        // 128

    int chunk = blockIdx.x & (NCH-1);
    int bh    = blockIdx.x >> 7;
    int tid   = threadIdx.x;

    // ticks for 128 k-rows (rows 64..127 are the current/query chunk)
    if (tid < 128) {
        int sp = (chunk*CHUNK + (SH - CHUNK) + tid) & (SH-1);
        int t  = g_sorted[bh*SH + sp];
        tick[tid] = t & (SEQ-1);
    }
    __syncthreads();

    // cooperative loads: Kt transposed (d-major), Vs row-major. 4 rows/iter.
    for (int rr = 0; rr < 128; rr += 4) {
        int row = rr + (tid >> 6);
        int d   = tid & 63;
        int s   = tick[row];
        int base = (bh*SEQ + s)*DIM + d;
        kt[d*KT_PITCH + row] = g_qk[base];
        vs[row*V_PITCH + d]  = g_v[base];
    }
    __syncthreads();

    // per-row key norm factor
    if (tid < 128) {
        float ss = 0.f;
#pragma unroll
        for (int d = 0; d < DIM; d++) { float x = kt[d*KT_PITCH + tid]; ss += x*x; }
        rnorm[tid] = rsqrtf(ss * (1.0f/DIM) + 1e-6f) * 0.125f;
    }
    __syncthreads();

    int tx = tid & 15;     // q group (4 queries)
    int ty = tid >> 4;     // kc group (8 keys)

    // dots: D[kc 8][q 4] per thread
    {
        float acc[8][4];
#pragma unroll
        for (int i = 0; i < 8; i++)
#pragma unroll
            for (int j = 0; j < 4; j++) acc[i][j] = 0.f;

#pragma unroll 4
        for (int d = 0; d < DIM; d++) {
            float a[8], b[4];
            const float* kr = &kt[d*KT_PITCH];
            *(float4*)(a)    = *(const float4*)&kr[ty*8];
            *(float4*)(a+4)  = *(const float4*)&kr[ty*8+4];
            *(float4*)(b)    = *(const float4*)&kr[64 + tx*4];
#pragma unroll
            for (int i = 0; i < 8; i++)
#pragma unroll
                for (int j = 0; j < 4; j++) acc[i][j] += a[i]*b[j];
        }

        int tq[4];
#pragma unroll
        for (int j = 0; j < 4; j++) tq[j] = tick[64 + tx*4 + j];

#pragma unroll
        for (int i = 0; i < 8; i++) {
            int kc = ty*8 + i;
            float rn = rnorm[kc];
            int tk = tick[kc];
            float4 o;
            float v0 = acc[i][0]*rn, v1 = acc[i][1]*rn,
                  v2 = acc[i][2]*rn, v3 = acc[i][3]*rn;
            if (tq[0] <  tk) v0 = -1e9f; else if (tq[0] == tk) v0 = -1e5f;
            if (tq[1] <  tk) v1 = -1e9f; else if (tq[1] == tk) v1 = -1e5f;
            if (tq[2] <  tk) v2 = -1e9f; else if (tq[2] == tk) v2 = -1e5f;
            if (tq[3] <  tk) v3 = -1e9f; else if (tq[3] == tk) v3 = -1e5f;
            o.x = v0; o.y = v1; o.z = v2; o.w = v3;
            *(float4*)&pt[kc*P_PITCH + tx*4] = o;
        }
    }
    __syncthreads();

    // softmax (logsumexp): 4 threads per q row, 32 cols each, shfl-combine
    {
        int row = tid >> 2, quar = tid & 3;
        float m = -3.4e38f;
        for (int c = 0; c < 32; c++)
            m = fmaxf(m, pt[(quar*32 + c)*P_PITCH + row]);
        m = fmaxf(m, __shfl_xor_sync(0xffffffffu, m, 1));
        m = fmaxf(m, __shfl_xor_sync(0xffffffffu, m, 2));
        float ssum = 0.f;
        for (int c = 0; c < 32; c++)
            ssum += __expf(pt[(quar*32 + c)*P_PITCH + row] - m);
        ssum += __shfl_xor_sync(0xffffffffu, ssum, 1);
        ssum += __shfl_xor_sync(0xffffffffu, ssum, 2);
        float lg = m + __logf(ssum);
        if (quar == 0) rowlog[row] = lg;
        for (int c = 0; c < 32; c++) {
            int idx = (quar*32 + c)*P_PITCH + row;
            pt[idx] = __expf(pt[idx] - lg);
        }
    }
    __syncthreads();

    // PV: O[q 4][d 4] per thread (ty -> q group of 4, tx -> d group of 4)
    {
        float acc2[4][4];
#pragma unroll
        for (int i = 0; i < 4; i++)
#pragma unroll
            for (int j = 0; j < 4; j++) acc2[i][j] = 0.f;

#pragma unroll 4
        for (int kc = 0; kc < 128; kc++) {
            float a2[4], b2[4];
            *(float4*)(a2) = *(const float4*)&pt[kc*P_PITCH + ty*4];
            *(float4*)(b2) = *(const float4*)&vs[kc*V_PITCH + tx*4];
#pragma unroll
            for (int i = 0; i < 4; i++)
#pragma unroll
                for (int j = 0; j < 4; j++) acc2[i][j] += a2[i]*b2[j];
        }

#pragma unroll
        for (int i = 0; i < 4; i++) {
            int q = ty*4 + i;
            float4 o; o.x = acc2[i][0]; o.y = acc2[i][1];
                      o.z = acc2[i][2]; o.w = acc2[i][3];
            *(float4*)&g_outs[((long)(bh*SH + chunk*CHUNK + q))*DIM + tx*4] = o;
        }
        if (tid < 64)
            g_logits[bh*SH + chunk*CHUNK + tid] = rowlog[tid];
    }
}

// ---------------- combine hash rounds + write output -----------------------
__global__ __launch_bounds__(256) void combine_kernel(float* __restrict__ out)
{
    int i = blockIdx.x*256 + threadIdx.x;
    int d  = i & 63;
    int r  = i >> 6;
    int s  = r & (SEQ-1);
    int bh = r >> 12;
    int base = bh*SH;

    int p0 = g_undo[base + s];
    int p1 = g_undo[base + SEQ + s];
    float l0 = g_logits[base + p0];
    float l1 = g_logits[base + p1];
    float m  = fmaxf(l0, l1);
    float w0 = __expf(l0 - m);
    float w1 = __expf(l1 - m);
    float inv = 1.0f / (w0 + w1);
    float o = (w0 * g_outs[(base + p0)*DIM + d] +
               w1 * g_outs[(base + p1)*DIM + d]) * inv;

    int b = bh >> 4, h = bh & 15;
    out[(b*SEQ + s)*(HEADS*DIM) + h*DIM + d] = o;
}

// ---------------- launch ---------------------------------------------------
extern "C" void kernel_launch(void* const* d_in, const int* in_sizes, int n_in,
                              void* d_out, int out_size)
{
    const float* hidden = (const float*)d_in[0];
    const float* Wqk    = (const float*)d_in[1];
    const float* Wv     = (const float*)d_in[2];
    const float* rot    = (const float*)d_in[3];
    float* out = (float*)d_out;

    static int attr_set = 0;
    if (!attr_set) {
        cudaFuncSetAttribute(attn_kernel,
                             cudaFuncAttributeMaxDynamicSharedMemorySize, ATTN_SMEM);
        attr_set = 1;
    }

    sgemm_kernel<<<dim3(8,64,2), 256>>>(hidden, Wqk, Wv);
    hash_kernel<<<(BH*SEQ)/HTOK, 128>>>(rot);
    sort_kernel<<<BH, 256>>>();
    attn_kernel<<<BH*NCH, 256, ATTN_SMEM>>>();
    combine_kernel<<<(BH*SEQ*DIM)/256, 256>>>(out);
}